// round 1
// baseline (speedup 1.0000x reference)
#include <cuda_runtime.h>
#include <math.h>

#define N_NODES 50000
#define N_EDGES 1600000
#define D_IN    128
#define D_HID   50
#define D_OUT   10

// ---------------- scratch (static __device__ globals; no runtime alloc) ----------------
__device__ float g_bufA[(size_t)N_NODES * D_IN];
__device__ float g_bufB[(size_t)N_NODES * D_IN];
__device__ float g_bufC[(size_t)N_NODES * D_IN];
__device__ float g_hid [(size_t)N_NODES * D_HID];
__device__ float g_deg [N_NODES];
__device__ float g_dinv[N_NODES];
__device__ int   g_row [N_EDGES];
__device__ int   g_col [N_EDGES];
__device__ float g_w   [N_EDGES];
__device__ int   g_is64;

// ---------------- utility ----------------
__global__ void zero_f(float* __restrict__ p, int n) {
    int i = blockIdx.x * blockDim.x + threadIdx.x;
    if (i < n) p[i] = 0.0f;
}

__global__ void negcopy_f4(const float* __restrict__ src, float* __restrict__ dst, int n4) {
    int i = blockIdx.x * blockDim.x + threadIdx.x;
    if (i < n4) {
        float4 v = ((const float4*)src)[i];
        v.x = -v.x; v.y = -v.y; v.z = -v.z; v.w = -v.w;
        ((float4*)dst)[i] = v;
    }
}

// ---------------- edge-index dtype detection ----------------
// If the buffer is int64 (values < 50000 >= 0), every high 32-bit word is 0.
// Check 256 high words; false positive prob for int32 data ~ (1/50000)^256 ~ 0.
__global__ void detect_kernel(const int* __restrict__ ei32) {
    __shared__ int any_nonzero;
    if (threadIdx.x == 0) any_nonzero = 0;
    __syncthreads();
    int v = ei32[2 * threadIdx.x + 1];
    if (v != 0) atomicExch(&any_nonzero, 1);
    __syncthreads();
    if (threadIdx.x == 0) g_is64 = (any_nonzero == 0) ? 1 : 0;
}

__device__ __forceinline__ int load_edge_idx(const void* ei, int pos) {
    if (g_is64) return (int)((const long long*)ei)[pos];
    return ((const int*)ei)[pos];
}

// ---------------- degree / normalization prep ----------------
__global__ void deg_kernel(const void* __restrict__ ei) {
    int e = blockIdx.x * blockDim.x + threadIdx.x;
    if (e >= N_EDGES) return;
    int r = load_edge_idx(ei, e);                 // edge_index[0][e]
    atomicAdd(&g_deg[r], 1.0f);
}

__global__ void dinv_kernel() {
    int n = blockIdx.x * blockDim.x + threadIdx.x;
    if (n >= N_NODES) return;
    float d = g_deg[n];
    g_dinv[n] = (d > 0.0f) ? rsqrtf(d) : 0.0f;
}

__global__ void prep_kernel(const void* __restrict__ ei) {
    int e = blockIdx.x * blockDim.x + threadIdx.x;
    if (e >= N_EDGES) return;
    int r = load_edge_idx(ei, e);
    int c = load_edge_idx(ei, N_EDGES + e);
    g_row[e] = r;
    g_col[e] = c;
    g_w[e] = -g_dinv[r] * g_dinv[c];
}

// ---------------- propagation: dst[row] += scale * w * src[col]  (warp per edge) ----------------
__global__ void prop_kernel(const float* __restrict__ src, float* __restrict__ dst, float scale) {
    int gt = blockIdx.x * blockDim.x + threadIdx.x;
    int e = gt >> 5;
    int lane = gt & 31;
    if (e >= N_EDGES) return;
    float w = g_w[e] * scale;
    int r = g_row[e];
    int c = g_col[e];
    const float4* s = (const float4*)(src + (size_t)c * D_IN);
    float4 v = __ldg(s + lane);
    float* d = dst + (size_t)r * D_IN + lane * 4;
    asm volatile("red.global.add.v4.f32 [%0], {%1, %2, %3, %4};"
                 :: "l"(d), "f"(w * v.x), "f"(w * v.y), "f"(w * v.z), "f"(w * v.w)
                 : "memory");
}

// ---------------- GEMM-accumulate: g_hid[n, 0:50] += A[n, 0:128] @ W[128, 50] ----------------
// 128 threads/block, thread per node. W in smem (padded to 52 cols -> LDS.128,
// uniform-address broadcast across the warp).
__global__ void gemm_accum(const float* __restrict__ A, const float* __restrict__ W) {
    __shared__ __align__(16) float Wsm[D_IN * 52];
    int tid = threadIdx.x;
    // thread tid loads W row tid (50 floats) + 2 pad zeros
    #pragma unroll 1
    for (int o = 0; o < D_HID; o++) Wsm[tid * 52 + o] = W[tid * D_HID + o];
    Wsm[tid * 52 + 50] = 0.0f;
    Wsm[tid * 52 + 51] = 0.0f;
    __syncthreads();

    int n = blockIdx.x * 128 + tid;
    if (n >= N_NODES) return;

    float acc[52];
    #pragma unroll
    for (int o = 0; o < 52; o++) acc[o] = 0.0f;

    const float4* Arow = (const float4*)(A + (size_t)n * D_IN);
    float4 a4 = __ldg(Arow);
    #pragma unroll 1
    for (int ic = 0; ic < 32; ic++) {
        float4 a_next;
        if (ic < 31) a_next = __ldg(Arow + ic + 1);
        float av[4] = {a4.x, a4.y, a4.z, a4.w};
        #pragma unroll
        for (int j = 0; j < 4; j++) {
            const float4* wrow = (const float4*)(Wsm + (ic * 4 + j) * 52);
            #pragma unroll
            for (int o4 = 0; o4 < 13; o4++) {
                float4 wv = wrow[o4];
                acc[o4 * 4 + 0] += av[j] * wv.x;
                acc[o4 * 4 + 1] += av[j] * wv.y;
                acc[o4 * 4 + 2] += av[j] * wv.z;
                acc[o4 * 4 + 3] += av[j] * wv.w;
            }
        }
        a4 = a_next;
    }

    float* Crow = g_hid + (size_t)n * D_HID;
    #pragma unroll
    for (int o = 0; o < D_HID; o++) Crow[o] += acc[o];
}

// ---------------- head: relu(hid + b) @ fc_w + fc_b -> log_softmax ----------------
__global__ void head_kernel(const float* __restrict__ cheb_b,
                            const float* __restrict__ fc_w,
                            const float* __restrict__ fc_b,
                            float* __restrict__ out) {
    __shared__ float s_fcw[D_HID * D_OUT];
    __shared__ float s_fcb[D_OUT];
    __shared__ float s_b[D_HID];
    int tid = threadIdx.x;
    for (int i = tid; i < D_HID * D_OUT; i += blockDim.x) s_fcw[i] = fc_w[i];
    if (tid < D_OUT) s_fcb[tid] = fc_b[tid];
    if (tid < D_HID) s_b[tid] = cheb_b[tid];
    __syncthreads();

    int n = blockIdx.x * blockDim.x + tid;
    if (n >= N_NODES) return;

    float l[D_OUT];
    #pragma unroll
    for (int o = 0; o < D_OUT; o++) l[o] = s_fcb[o];

    const float* hrow = g_hid + (size_t)n * D_HID;
    #pragma unroll 1
    for (int j = 0; j < D_HID; j++) {
        float h = hrow[j] + s_b[j];
        h = fmaxf(h, 0.0f);
        #pragma unroll
        for (int o = 0; o < D_OUT; o++) l[o] += h * s_fcw[j * D_OUT + o];
    }

    float m = l[0];
    #pragma unroll
    for (int o = 1; o < D_OUT; o++) m = fmaxf(m, l[o]);
    float s = 0.0f;
    #pragma unroll
    for (int o = 0; o < D_OUT; o++) s += expf(l[o] - m);
    float lse = m + logf(s);
    #pragma unroll
    for (int o = 0; o < D_OUT; o++) out[(size_t)n * D_OUT + o] = l[o] - lse;
}

// ---------------- launch ----------------
extern "C" void kernel_launch(void* const* d_in, const int* in_sizes, int n_in,
                              void* d_out, int out_size) {
    const float* x      = (const float*)d_in[0];
    const void*  ei     = d_in[1];                 // int32 or int64, detected on device
    const float* cheb_w = (const float*)d_in[2];   // [5][128][50]
    const float* cheb_b = (const float*)d_in[3];
    const float* fc_w   = (const float*)d_in[4];
    const float* fc_b   = (const float*)d_in[5];
    float* out = (float*)d_out;

    float *bufA, *bufB, *bufC, *hid, *deg;
    cudaGetSymbolAddress((void**)&bufA, g_bufA);
    cudaGetSymbolAddress((void**)&bufB, g_bufB);
    cudaGetSymbolAddress((void**)&bufC, g_bufC);
    cudaGetSymbolAddress((void**)&hid,  g_hid);
    cudaGetSymbolAddress((void**)&deg,  g_deg);

    const int TB = 256;
    const int NODE_BLK = (N_NODES + TB - 1) / TB;
    const int EDGE_BLK = (N_EDGES + TB - 1) / TB;
    const int GEMM_BLK = (N_NODES + 127) / 128;
    const int FEAT_N   = N_NODES * D_IN;
    const int FEAT_BLK = (FEAT_N + TB - 1) / TB;
    const int F4_N     = FEAT_N / 4;
    const int F4_BLK   = (F4_N + TB - 1) / TB;
    // warp per edge
    const long long PROP_T = (long long)N_EDGES * 32;
    const int PROP_BLK = (int)((PROP_T + TB - 1) / TB);

    // prep: degree, dinv, edge weights
    detect_kernel<<<1, 256>>>((const int*)ei);
    zero_f<<<NODE_BLK, TB>>>(deg, N_NODES);
    zero_f<<<(N_NODES * D_HID + TB - 1) / TB, TB>>>(hid, N_NODES * D_HID);
    deg_kernel<<<EDGE_BLK, TB>>>(ei);
    dinv_kernel<<<NODE_BLK, TB>>>();
    prep_kernel<<<EDGE_BLK, TB>>>(ei);

    const int WSTRIDE = D_IN * D_HID;

    // k=0: hid += x @ W0
    gemm_accum<<<GEMM_BLK, 128>>>(x, cheb_w + 0 * WSTRIDE);

    // k=1: tx1 = L_hat @ x (bufA)
    zero_f<<<FEAT_BLK, TB>>>(bufA, FEAT_N);
    prop_kernel<<<PROP_BLK, TB>>>(x, bufA, 1.0f);
    gemm_accum<<<GEMM_BLK, 128>>>(bufA, cheb_w + 1 * WSTRIDE);

    // k=2: tx2 = 2*L@tx1 - x (bufB)
    negcopy_f4<<<F4_BLK, TB>>>(x, bufB, F4_N);
    prop_kernel<<<PROP_BLK, TB>>>(bufA, bufB, 2.0f);
    gemm_accum<<<GEMM_BLK, 128>>>(bufB, cheb_w + 2 * WSTRIDE);

    // k=3: tx3 = 2*L@tx2 - tx1 (bufC)
    negcopy_f4<<<F4_BLK, TB>>>(bufA, bufC, F4_N);
    prop_kernel<<<PROP_BLK, TB>>>(bufB, bufC, 2.0f);
    gemm_accum<<<GEMM_BLK, 128>>>(bufC, cheb_w + 3 * WSTRIDE);

    // k=4: tx4 = 2*L@tx3 - tx2 (bufA reused)
    negcopy_f4<<<F4_BLK, TB>>>(bufB, bufA, F4_N);
    prop_kernel<<<PROP_BLK, TB>>>(bufC, bufA, 2.0f);
    gemm_accum<<<GEMM_BLK, 128>>>(bufA, cheb_w + 4 * WSTRIDE);

    // head
    head_kernel<<<(N_NODES + 127) / 128, 128>>>(cheb_b, fc_w, fc_b, out);
}

// round 2
// speedup vs baseline: 2.1233x; 2.1233x over previous
#include <cuda_runtime.h>
#include <math.h>

#define N_NODES 50000
#define N_EDGES 1600000
#define D_IN    128
#define D_HID   50
#define D_OUT   10
#define STRIDE  64   // padded row stride (floats) for 50-dim node buffers

// ---------------- static scratch ----------------
__device__ float g_P [(size_t)5 * N_NODES * STRIDE];  // projections x @ W_k
__device__ float g_b3[(size_t)N_NODES * STRIDE];
__device__ float g_b2[(size_t)N_NODES * STRIDE];
__device__ float g_b1[(size_t)N_NODES * STRIDE];
__device__ float g_H [(size_t)N_NODES * STRIDE];      // final hidden (pre-bias/relu)
__device__ int   g_deg   [N_NODES];
__device__ float g_dinv  [N_NODES];
__device__ int   g_rowptr[N_NODES + 1];
__device__ int   g_cursor[N_NODES];
__device__ int2  g_csr   [N_EDGES];                   // {col, w as float bits}
__device__ int   g_is64;

// ---------------- edge-index dtype detection ----------------
__global__ void detect_kernel(const int* __restrict__ ei32) {
    __shared__ int any_nonzero;
    if (threadIdx.x == 0) any_nonzero = 0;
    __syncthreads();
    int v = ei32[2 * threadIdx.x + 1];
    if (v != 0) atomicExch(&any_nonzero, 1);
    __syncthreads();
    if (threadIdx.x == 0) g_is64 = (any_nonzero == 0) ? 1 : 0;
}

__device__ __forceinline__ int load_edge_idx(const void* ei, int pos) {
    if (g_is64) return (int)((const long long*)ei)[pos];
    return ((const int*)ei)[pos];
}

// ---------------- CSR construction ----------------
__global__ void zero_deg_kernel() {
    int i = blockIdx.x * blockDim.x + threadIdx.x;
    if (i < N_NODES) g_deg[i] = 0;
}

__global__ void deg_kernel(const void* __restrict__ ei) {
    int e = blockIdx.x * blockDim.x + threadIdx.x;
    if (e >= N_EDGES) return;
    int r = load_edge_idx(ei, e);
    atomicAdd(&g_deg[r], 1);
}

__global__ void dinv_kernel() {
    int n = blockIdx.x * blockDim.x + threadIdx.x;
    if (n >= N_NODES) return;
    int d = g_deg[n];
    g_dinv[n] = (d > 0) ? rsqrtf((float)d) : 0.0f;
}

// single-block exclusive scan of degrees -> row_ptr (+ cursor copy)
__global__ void scan_kernel() {
    __shared__ int part[1024];
    const int CH = (N_NODES + 1023) / 1024;  // 49
    int t = threadIdx.x;
    int base = t * CH;
    int s = 0;
    #pragma unroll 1
    for (int i = 0; i < CH; i++) {
        int idx = base + i;
        if (idx < N_NODES) s += g_deg[idx];
    }
    part[t] = s;
    __syncthreads();
    // Hillis-Steele inclusive scan
    for (int off = 1; off < 1024; off <<= 1) {
        int v = (t >= off) ? part[t - off] : 0;
        __syncthreads();
        part[t] += v;
        __syncthreads();
    }
    int run = (t == 0) ? 0 : part[t - 1];
    #pragma unroll 1
    for (int i = 0; i < CH; i++) {
        int idx = base + i;
        if (idx < N_NODES) {
            g_rowptr[idx] = run;
            g_cursor[idx] = run;
            run += g_deg[idx];
        }
    }
    if (t == 1023) g_rowptr[N_NODES] = run;  // == N_EDGES
}

__global__ void scatter_kernel(const void* __restrict__ ei) {
    int e = blockIdx.x * blockDim.x + threadIdx.x;
    if (e >= N_EDGES) return;
    int r = load_edge_idx(ei, e);
    int c = load_edge_idx(ei, N_EDGES + e);
    float w = -g_dinv[r] * g_dinv[c];
    int pos = atomicAdd(&g_cursor[r], 1);
    g_csr[pos] = make_int2(c, __float_as_int(w));
}

// ---------------- projection: P_k[n, 0:50] = x[n, 0:128] @ W_k[128, 50] ----------------
// 128 threads/block, thread-per-node; W_k in smem padded to 52 cols (LDS.128 broadcast).
__global__ void proj_kernel(const float* __restrict__ x, const float* __restrict__ cheb_w) {
    __shared__ __align__(16) float Wsm[D_IN * 52];
    int tid = threadIdx.x;
    int k = blockIdx.y;
    const float* W = cheb_w + (size_t)k * D_IN * D_HID;
    #pragma unroll 1
    for (int o = 0; o < D_HID; o++) Wsm[tid * 52 + o] = W[tid * D_HID + o];
    Wsm[tid * 52 + 50] = 0.0f;
    Wsm[tid * 52 + 51] = 0.0f;
    __syncthreads();

    int n = blockIdx.x * 128 + tid;
    if (n >= N_NODES) return;

    float acc[52];
    #pragma unroll
    for (int o = 0; o < 52; o++) acc[o] = 0.0f;

    const float4* Arow = (const float4*)(x + (size_t)n * D_IN);
    float4 a4 = __ldg(Arow);
    #pragma unroll 1
    for (int ic = 0; ic < 32; ic++) {
        float4 a_next;
        if (ic < 31) a_next = __ldg(Arow + ic + 1);
        float av[4] = {a4.x, a4.y, a4.z, a4.w};
        #pragma unroll
        for (int j = 0; j < 4; j++) {
            const float4* wrow = (const float4*)(Wsm + (ic * 4 + j) * 52);
            #pragma unroll
            for (int o4 = 0; o4 < 13; o4++) {
                float4 wv = wrow[o4];
                acc[o4 * 4 + 0] += av[j] * wv.x;
                acc[o4 * 4 + 1] += av[j] * wv.y;
                acc[o4 * 4 + 2] += av[j] * wv.z;
                acc[o4 * 4 + 3] += av[j] * wv.w;
            }
        }
        a4 = a_next;
    }

    float* dst = g_P + ((size_t)k * N_NODES + n) * STRIDE;
    #pragma unroll
    for (int o = 0; o < D_HID; o++) dst[o] = acc[o];
}

// ---------------- Clenshaw propagation (CSR, warp-per-row, no atomics) ----------------
// dst[row] = P[row] + scale * sum_e w_e * src[col_e] - (sub ? sub[row] : 0)
__global__ void prop_csr(const float* __restrict__ src, const float* __restrict__ P,
                         const float* __restrict__ sub, float scale,
                         float* __restrict__ dst) {
    int gw = (blockIdx.x * blockDim.x + threadIdx.x) >> 5;
    int lane = threadIdx.x & 31;
    if (gw >= N_NODES) return;
    int s = g_rowptr[gw];
    int e = g_rowptr[gw + 1];
    const bool act = lane < 25;  // 25 lanes x float2 = 50 floats
    const float2* s2 = (const float2*)src;
    float ax = 0.0f, ay = 0.0f;

    int i = s;
    for (; i + 1 < e; i += 2) {
        int2 m0 = __ldg(&g_csr[i]);
        int2 m1 = __ldg(&g_csr[i + 1]);
        float2 v0, v1;
        if (act) {
            v0 = __ldg(s2 + (size_t)m0.x * (STRIDE / 2) + lane);
            v1 = __ldg(s2 + (size_t)m1.x * (STRIDE / 2) + lane);
        }
        float w0 = __int_as_float(m0.y);
        float w1 = __int_as_float(m1.y);
        if (act) {
            ax += w0 * v0.x; ay += w0 * v0.y;
            ax += w1 * v1.x; ay += w1 * v1.y;
        }
    }
    if (i < e) {
        int2 m = __ldg(&g_csr[i]);
        if (act) {
            float2 v = __ldg(s2 + (size_t)m.x * (STRIDE / 2) + lane);
            float w = __int_as_float(m.y);
            ax += w * v.x; ay += w * v.y;
        }
    }

    if (act) {
        size_t off = (size_t)gw * (STRIDE / 2) + lane;
        float2 p = __ldg((const float2*)P + off);
        float rx = p.x + scale * ax;
        float ry = p.y + scale * ay;
        if (sub) {
            float2 sb = __ldg((const float2*)sub + off);
            rx -= sb.x; ry -= sb.y;
        }
        float2 r; r.x = rx; r.y = ry;
        ((float2*)dst)[off] = r;
    }
}

// ---------------- head: relu(H + b) @ fc_w + fc_b -> log_softmax ----------------
__global__ void head_kernel(const float* __restrict__ cheb_b,
                            const float* __restrict__ fc_w,
                            const float* __restrict__ fc_b,
                            float* __restrict__ out) {
    __shared__ float s_fcw[D_HID * D_OUT];
    __shared__ float s_fcb[D_OUT];
    __shared__ float s_b[D_HID];
    int tid = threadIdx.x;
    for (int i = tid; i < D_HID * D_OUT; i += blockDim.x) s_fcw[i] = fc_w[i];
    if (tid < D_OUT) s_fcb[tid] = fc_b[tid];
    if (tid < D_HID) s_b[tid] = cheb_b[tid];
    __syncthreads();

    int n = blockIdx.x * blockDim.x + tid;
    if (n >= N_NODES) return;

    float l[D_OUT];
    #pragma unroll
    for (int o = 0; o < D_OUT; o++) l[o] = s_fcb[o];

    const float* hrow = g_H + (size_t)n * STRIDE;
    #pragma unroll 1
    for (int j = 0; j < D_HID; j++) {
        float h = hrow[j] + s_b[j];
        h = fmaxf(h, 0.0f);
        #pragma unroll
        for (int o = 0; o < D_OUT; o++) l[o] += h * s_fcw[j * D_OUT + o];
    }

    float m = l[0];
    #pragma unroll
    for (int o = 1; o < D_OUT; o++) m = fmaxf(m, l[o]);
    float s = 0.0f;
    #pragma unroll
    for (int o = 0; o < D_OUT; o++) s += expf(l[o] - m);
    float lse = m + logf(s);
    #pragma unroll
    for (int o = 0; o < D_OUT; o++) out[(size_t)n * D_OUT + o] = l[o] - lse;
}

// ---------------- launch ----------------
extern "C" void kernel_launch(void* const* d_in, const int* in_sizes, int n_in,
                              void* d_out, int out_size) {
    const float* x      = (const float*)d_in[0];
    const void*  ei     = d_in[1];
    const float* cheb_w = (const float*)d_in[2];
    const float* cheb_b = (const float*)d_in[3];
    const float* fc_w   = (const float*)d_in[4];
    const float* fc_b   = (const float*)d_in[5];
    float* out = (float*)d_out;

    float *P, *b3, *b2, *b1, *H;
    cudaGetSymbolAddress((void**)&P,  g_P);
    cudaGetSymbolAddress((void**)&b3, g_b3);
    cudaGetSymbolAddress((void**)&b2, g_b2);
    cudaGetSymbolAddress((void**)&b1, g_b1);
    cudaGetSymbolAddress((void**)&H,  g_H);
    const size_t PS = (size_t)N_NODES * STRIDE;
    float* P0 = P + 0 * PS;
    float* P1 = P + 1 * PS;
    float* P2 = P + 2 * PS;
    float* P3 = P + 3 * PS;
    float* P4 = P + 4 * PS;

    const int TB = 256;
    const int NODE_BLK = (N_NODES + TB - 1) / TB;
    const int EDGE_BLK = (N_EDGES + TB - 1) / TB;
    // warp per node row
    const long long PT = (long long)N_NODES * 32;
    const int PROP_BLK = (int)((PT + TB - 1) / TB);

    // ---- CSR build ----
    detect_kernel<<<1, 256>>>((const int*)ei);
    zero_deg_kernel<<<NODE_BLK, TB>>>();
    deg_kernel<<<EDGE_BLK, TB>>>(ei);
    dinv_kernel<<<NODE_BLK, TB>>>();
    scan_kernel<<<1, 1024>>>();
    scatter_kernel<<<EDGE_BLK, TB>>>(ei);

    // ---- projections: P_k = x @ W_k for k=0..4 ----
    dim3 pg((N_NODES + 127) / 128, 5);
    proj_kernel<<<pg, 128>>>(x, cheb_w);

    // ---- Clenshaw: b4 = P4
    //      b3 = P3 + 2L b4
    //      b2 = P2 + 2L b3 - P4
    //      b1 = P1 + 2L b2 - b3
    //      H  = P0 +  L b1 - b2
    prop_csr<<<PROP_BLK, TB>>>(P4, P3, nullptr, 2.0f, b3);
    prop_csr<<<PROP_BLK, TB>>>(b3, P2, P4,      2.0f, b2);
    prop_csr<<<PROP_BLK, TB>>>(b2, P1, b3,      2.0f, b1);
    prop_csr<<<PROP_BLK, TB>>>(b1, P0, b2,      1.0f, H);

    // ---- head ----
    head_kernel<<<(N_NODES + 127) / 128, 128>>>(cheb_b, fc_w, fc_b, out);
}

// round 3
// speedup vs baseline: 2.6426x; 1.2446x over previous
#include <cuda_runtime.h>
#include <math.h>

#define N_NODES 50000
#define N_EDGES 1600000
#define D_IN    128
#define D_HID   50
#define D_OUT   10
#define STRIDE  64   // padded row stride (floats) for 50-dim node buffers

// ---------------- static scratch ----------------
__device__ float g_P [(size_t)5 * N_NODES * STRIDE];  // projections x @ W_k
__device__ float g_b3[(size_t)N_NODES * STRIDE];
__device__ float g_b2[(size_t)N_NODES * STRIDE];
__device__ float g_b1[(size_t)N_NODES * STRIDE];
__device__ int   g_deg   [N_NODES];
__device__ float g_dinv  [N_NODES];
__device__ int   g_rowptr[N_NODES + 1];
__device__ int   g_cursor[N_NODES];
__device__ int2  g_csr   [N_EDGES];                   // {col, w as float bits}
__device__ int   g_is64;

// ---------------- edge-index dtype detection ----------------
__global__ void detect_kernel(const int* __restrict__ ei32) {
    __shared__ int any_nonzero;
    if (threadIdx.x == 0) any_nonzero = 0;
    __syncthreads();
    int v = ei32[2 * threadIdx.x + 1];
    if (v != 0) atomicExch(&any_nonzero, 1);
    __syncthreads();
    if (threadIdx.x == 0) g_is64 = (any_nonzero == 0) ? 1 : 0;
}

__device__ __forceinline__ int load_edge_idx(const void* ei, int pos) {
    if (g_is64) return (int)((const long long*)ei)[pos];
    return ((const int*)ei)[pos];
}

// ---------------- CSR construction ----------------
__global__ void zero_deg_kernel() {
    int i = blockIdx.x * blockDim.x + threadIdx.x;
    if (i < N_NODES) g_deg[i] = 0;
}

__global__ void deg_kernel(const void* __restrict__ ei) {
    int e = blockIdx.x * blockDim.x + threadIdx.x;
    if (e >= N_EDGES) return;
    int r = load_edge_idx(ei, e);
    atomicAdd(&g_deg[r], 1);
}

__global__ void dinv_kernel() {
    int n = blockIdx.x * blockDim.x + threadIdx.x;
    if (n >= N_NODES) return;
    int d = g_deg[n];
    g_dinv[n] = (d > 0) ? rsqrtf((float)d) : 0.0f;
}

// single-block exclusive scan of degrees -> row_ptr (+ cursor copy)
__global__ void scan_kernel() {
    __shared__ int part[1024];
    const int CH = (N_NODES + 1023) / 1024;  // 49
    int t = threadIdx.x;
    int base = t * CH;
    int s = 0;
    #pragma unroll 1
    for (int i = 0; i < CH; i++) {
        int idx = base + i;
        if (idx < N_NODES) s += g_deg[idx];
    }
    part[t] = s;
    __syncthreads();
    for (int off = 1; off < 1024; off <<= 1) {
        int v = (t >= off) ? part[t - off] : 0;
        __syncthreads();
        part[t] += v;
        __syncthreads();
    }
    int run = (t == 0) ? 0 : part[t - 1];
    #pragma unroll 1
    for (int i = 0; i < CH; i++) {
        int idx = base + i;
        if (idx < N_NODES) {
            g_rowptr[idx] = run;
            g_cursor[idx] = run;
            run += g_deg[idx];
        }
    }
    if (t == 1023) g_rowptr[N_NODES] = run;
}

__global__ void scatter_kernel(const void* __restrict__ ei) {
    int e = blockIdx.x * blockDim.x + threadIdx.x;
    if (e >= N_EDGES) return;
    int r = load_edge_idx(ei, e);
    int c = load_edge_idx(ei, N_EDGES + e);
    float w = -g_dinv[r] * g_dinv[c];
    int pos = atomicAdd(&g_cursor[r], 1);
    g_csr[pos] = make_int2(c, __float_as_int(w));
}

// ---------------- projection: P_k[n, 0:50] = x[n, 0:128] @ W_k[128, 50] ----------------
// 128 threads/block, 2 nodes per thread; W_k in smem padded to 52 cols.
__global__ void __launch_bounds__(128) proj_kernel(const float* __restrict__ x,
                                                   const float* __restrict__ cheb_w) {
    __shared__ __align__(16) float Wsm[D_IN * 52];
    int tid = threadIdx.x;
    int k = blockIdx.y;
    const float* W = cheb_w + (size_t)k * D_IN * D_HID;
    #pragma unroll 1
    for (int o = 0; o < D_HID; o++) Wsm[tid * 52 + o] = W[tid * D_HID + o];
    Wsm[tid * 52 + 50] = 0.0f;
    Wsm[tid * 52 + 51] = 0.0f;
    __syncthreads();

    int n0 = blockIdx.x * 256 + tid;
    int n1 = n0 + 128;
    bool v0 = n0 < N_NODES;
    bool v1 = n1 < N_NODES;

    float acc0[52], acc1[52];
    #pragma unroll
    for (int o = 0; o < 52; o++) { acc0[o] = 0.0f; acc1[o] = 0.0f; }

    const float4* A0 = (const float4*)(x + (size_t)n0 * D_IN);
    const float4* A1 = (const float4*)(x + (size_t)n1 * D_IN);
    float4 z4 = make_float4(0.f, 0.f, 0.f, 0.f);
    float4 a0 = v0 ? __ldg(A0) : z4;
    float4 a1 = v1 ? __ldg(A1) : z4;

    #pragma unroll 1
    for (int ic = 0; ic < 32; ic++) {
        float4 a0n = z4, a1n = z4;
        if (ic < 31) {
            if (v0) a0n = __ldg(A0 + ic + 1);
            if (v1) a1n = __ldg(A1 + ic + 1);
        }
        float av0[4] = {a0.x, a0.y, a0.z, a0.w};
        float av1[4] = {a1.x, a1.y, a1.z, a1.w};
        #pragma unroll
        for (int j = 0; j < 4; j++) {
            const float4* wrow = (const float4*)(Wsm + (ic * 4 + j) * 52);
            #pragma unroll
            for (int o4 = 0; o4 < 13; o4++) {
                float4 wv = wrow[o4];
                acc0[o4 * 4 + 0] = fmaf(av0[j], wv.x, acc0[o4 * 4 + 0]);
                acc0[o4 * 4 + 1] = fmaf(av0[j], wv.y, acc0[o4 * 4 + 1]);
                acc0[o4 * 4 + 2] = fmaf(av0[j], wv.z, acc0[o4 * 4 + 2]);
                acc0[o4 * 4 + 3] = fmaf(av0[j], wv.w, acc0[o4 * 4 + 3]);
                acc1[o4 * 4 + 0] = fmaf(av1[j], wv.x, acc1[o4 * 4 + 0]);
                acc1[o4 * 4 + 1] = fmaf(av1[j], wv.y, acc1[o4 * 4 + 1]);
                acc1[o4 * 4 + 2] = fmaf(av1[j], wv.z, acc1[o4 * 4 + 2]);
                acc1[o4 * 4 + 3] = fmaf(av1[j], wv.w, acc1[o4 * 4 + 3]);
            }
        }
        a0 = a0n; a1 = a1n;
    }

    if (v0) {
        float* dst = g_P + ((size_t)k * N_NODES + n0) * STRIDE;
        #pragma unroll
        for (int o4 = 0; o4 < 12; o4++)
            ((float4*)dst)[o4] = make_float4(acc0[o4*4], acc0[o4*4+1], acc0[o4*4+2], acc0[o4*4+3]);
        ((float2*)dst)[24] = make_float2(acc0[48], acc0[49]);
    }
    if (v1) {
        float* dst = g_P + ((size_t)k * N_NODES + n1) * STRIDE;
        #pragma unroll
        for (int o4 = 0; o4 < 12; o4++)
            ((float4*)dst)[o4] = make_float4(acc1[o4*4], acc1[o4*4+1], acc1[o4*4+2], acc1[o4*4+3]);
        ((float2*)dst)[24] = make_float2(acc1[48], acc1[49]);
    }
}

// ---------------- shared accumulate: 4-edge unroll, dual accumulators ----------------
__device__ __forceinline__ void row_accumulate(const float2* __restrict__ s2p,
                                               int s, int e, bool act, int lane,
                                               float& axo, float& ayo) {
    float ax0 = 0.f, ay0 = 0.f, ax1 = 0.f, ay1 = 0.f;
    int i = s;
    #pragma unroll 1
    for (; i + 4 <= e; i += 4) {
        int2 m0 = __ldg(&g_csr[i]);
        int2 m1 = __ldg(&g_csr[i + 1]);
        int2 m2 = __ldg(&g_csr[i + 2]);
        int2 m3 = __ldg(&g_csr[i + 3]);
        if (act) {
            float2 v0 = __ldg(s2p + (size_t)m0.x * (STRIDE / 2) + lane);
            float2 v1 = __ldg(s2p + (size_t)m1.x * (STRIDE / 2) + lane);
            float2 v2 = __ldg(s2p + (size_t)m2.x * (STRIDE / 2) + lane);
            float2 v3 = __ldg(s2p + (size_t)m3.x * (STRIDE / 2) + lane);
            float w0 = __int_as_float(m0.y), w1 = __int_as_float(m1.y);
            float w2 = __int_as_float(m2.y), w3 = __int_as_float(m3.y);
            ax0 = fmaf(w0, v0.x, ax0); ay0 = fmaf(w0, v0.y, ay0);
            ax1 = fmaf(w1, v1.x, ax1); ay1 = fmaf(w1, v1.y, ay1);
            ax0 = fmaf(w2, v2.x, ax0); ay0 = fmaf(w2, v2.y, ay0);
            ax1 = fmaf(w3, v3.x, ax1); ay1 = fmaf(w3, v3.y, ay1);
        }
    }
    #pragma unroll 1
    for (; i < e; i++) {
        int2 m = __ldg(&g_csr[i]);
        if (act) {
            float2 v = __ldg(s2p + (size_t)m.x * (STRIDE / 2) + lane);
            float w = __int_as_float(m.y);
            ax0 = fmaf(w, v.x, ax0); ay0 = fmaf(w, v.y, ay0);
        }
    }
    axo = ax0 + ax1;
    ayo = ay0 + ay1;
}

// ---------------- Clenshaw propagation (CSR, warp-per-row) ----------------
// dst[row] = P[row] + scale * sum_e w_e * src[col_e] - (sub ? sub[row] : 0)
__global__ void __launch_bounds__(256) prop_csr(const float* __restrict__ src,
                                                const float* __restrict__ P,
                                                const float* __restrict__ sub, float scale,
                                                float* __restrict__ dst) {
    int gw = (blockIdx.x * blockDim.x + threadIdx.x) >> 5;
    int lane = threadIdx.x & 31;
    if (gw >= N_NODES) return;
    int s = __ldg(&g_rowptr[gw]);
    int e = __ldg(&g_rowptr[gw + 1]);
    const bool act = lane < 25;
    float ax, ay;
    row_accumulate((const float2*)src, s, e, act, lane, ax, ay);

    if (act) {
        size_t off = (size_t)gw * (STRIDE / 2) + lane;
        float2 p = __ldg((const float2*)P + off);
        float rx = fmaf(scale, ax, p.x);
        float ry = fmaf(scale, ay, p.y);
        if (sub) {
            float2 sb = __ldg((const float2*)sub + off);
            rx -= sb.x; ry -= sb.y;
        }
        ((float2*)dst)[off] = make_float2(rx, ry);
    }
}

// ---------------- last prop fused with head: relu -> 50x10 matvec -> log_softmax ----------------
__global__ void __launch_bounds__(256) prop_csr_head(const float* __restrict__ src,
                                                     const float* __restrict__ P,
                                                     const float* __restrict__ sub,
                                                     const float* __restrict__ cheb_b,
                                                     const float* __restrict__ fc_w,
                                                     const float* __restrict__ fc_b,
                                                     float* __restrict__ out) {
    // transposed fc_w: s_fcwT[o][j], row stride 52 (even -> float2-aligned pairs)
    __shared__ __align__(8) float s_fcwT[D_OUT * 52];
    __shared__ float s_b[D_HID];
    __shared__ float s_fcb[D_OUT];
    int tid = threadIdx.x;
    for (int i = tid; i < D_HID * D_OUT; i += blockDim.x) {
        int j = i / D_OUT, o = i % D_OUT;
        s_fcwT[o * 52 + j] = fc_w[i];
    }
    if (tid < D_OUT) { s_fcwT[tid * 52 + 50] = 0.f; s_fcwT[tid * 52 + 51] = 0.f; }
    if (tid < D_HID) s_b[tid] = cheb_b[tid];
    if (tid < D_OUT) s_fcb[tid] = fc_b[tid];
    __syncthreads();

    int gw = (blockIdx.x * blockDim.x + tid) >> 5;
    int lane = tid & 31;
    if (gw >= N_NODES) return;
    int s = __ldg(&g_rowptr[gw]);
    int e = __ldg(&g_rowptr[gw + 1]);
    const bool act = lane < 25;
    float ax, ay;
    row_accumulate((const float2*)src, s, e, act, lane, ax, ay);

    float l[D_OUT];
    if (act) {
        size_t off = (size_t)gw * (STRIDE / 2) + lane;
        float2 p  = __ldg((const float2*)P + off);
        float2 sb = __ldg((const float2*)sub + off);
        float hx = fmaxf(p.x + ax - sb.x + s_b[2 * lane],     0.0f);   // scale = 1
        float hy = fmaxf(p.y + ay - sb.y + s_b[2 * lane + 1], 0.0f);
        #pragma unroll
        for (int o = 0; o < D_OUT; o++) {
            float2 w2 = ((const float2*)(s_fcwT + o * 52))[lane];
            l[o] = hx * w2.x + hy * w2.y;
        }
    } else {
        #pragma unroll
        for (int o = 0; o < D_OUT; o++) l[o] = 0.0f;
    }

    #pragma unroll
    for (int offm = 16; offm > 0; offm >>= 1) {
        #pragma unroll
        for (int o = 0; o < D_OUT; o++)
            l[o] += __shfl_xor_sync(0xffffffffu, l[o], offm);
    }

    if (lane == 0) {
        #pragma unroll
        for (int o = 0; o < D_OUT; o++) l[o] += s_fcb[o];
        float m = l[0];
        #pragma unroll
        for (int o = 1; o < D_OUT; o++) m = fmaxf(m, l[o]);
        float ssum = 0.0f;
        #pragma unroll
        for (int o = 0; o < D_OUT; o++) ssum += expf(l[o] - m);
        float lse = m + logf(ssum);
        float* orow = out + (size_t)gw * D_OUT;
        #pragma unroll
        for (int o = 0; o < D_OUT; o++) orow[o] = l[o] - lse;
    }
}

// ---------------- launch ----------------
extern "C" void kernel_launch(void* const* d_in, const int* in_sizes, int n_in,
                              void* d_out, int out_size) {
    const float* x      = (const float*)d_in[0];
    const void*  ei     = d_in[1];
    const float* cheb_w = (const float*)d_in[2];
    const float* cheb_b = (const float*)d_in[3];
    const float* fc_w   = (const float*)d_in[4];
    const float* fc_b   = (const float*)d_in[5];
    float* out = (float*)d_out;

    float *P, *b3, *b2, *b1;
    cudaGetSymbolAddress((void**)&P,  g_P);
    cudaGetSymbolAddress((void**)&b3, g_b3);
    cudaGetSymbolAddress((void**)&b2, g_b2);
    cudaGetSymbolAddress((void**)&b1, g_b1);
    const size_t PS = (size_t)N_NODES * STRIDE;
    float* P0 = P + 0 * PS;
    float* P1 = P + 1 * PS;
    float* P2 = P + 2 * PS;
    float* P3 = P + 3 * PS;
    float* P4 = P + 4 * PS;

    const int TB = 256;
    const int NODE_BLK = (N_NODES + TB - 1) / TB;
    const int EDGE_BLK = (N_EDGES + TB - 1) / TB;
    const long long PT = (long long)N_NODES * 32;
    const int PROP_BLK = (int)((PT + TB - 1) / TB);
    dim3 pg((N_NODES + 255) / 256, 5);

    // lazily-created side stream for proj overlap (created once, outside capture)
    static cudaStream_t s_proj = nullptr;
    static cudaEvent_t ev_fork = nullptr, ev_proj = nullptr;
    static int use_async = -1;
    if (use_async < 0) {
        bool ok = (cudaStreamCreateWithFlags(&s_proj, cudaStreamNonBlocking) == cudaSuccess);
        ok = ok && (cudaEventCreateWithFlags(&ev_fork, cudaEventDisableTiming) == cudaSuccess);
        ok = ok && (cudaEventCreateWithFlags(&ev_proj, cudaEventDisableTiming) == cudaSuccess);
        use_async = ok ? 1 : 0;
    }

    // ---- fork: projections P_k = x @ W_k run concurrently with CSR build ----
    if (use_async) {
        cudaEventRecord(ev_fork, 0);
        cudaStreamWaitEvent(s_proj, ev_fork, 0);
        proj_kernel<<<pg, 128, 0, s_proj>>>(x, cheb_w);
        cudaEventRecord(ev_proj, s_proj);
    }

    // ---- CSR build (main stream) ----
    detect_kernel<<<1, 256>>>((const int*)ei);
    zero_deg_kernel<<<NODE_BLK, TB>>>();
    deg_kernel<<<EDGE_BLK, TB>>>(ei);
    dinv_kernel<<<NODE_BLK, TB>>>();
    scan_kernel<<<1, 1024>>>();
    scatter_kernel<<<EDGE_BLK, TB>>>(ei);

    if (use_async) {
        cudaStreamWaitEvent(0, ev_proj, 0);   // join
    } else {
        proj_kernel<<<pg, 128>>>(x, cheb_w);
    }

    // ---- Clenshaw: b4 = P4
    //      b3 = P3 + 2L b4
    //      b2 = P2 + 2L b3 - P4
    //      b1 = P1 + 2L b2 - b3
    //      out = head(P0 + L b1 - b2)
    prop_csr<<<PROP_BLK, TB>>>(P4, P3, nullptr, 2.0f, b3);
    prop_csr<<<PROP_BLK, TB>>>(b3, P2, P4,      2.0f, b2);
    prop_csr<<<PROP_BLK, TB>>>(b2, P1, b3,      2.0f, b1);
    prop_csr_head<<<PROP_BLK, TB>>>(b1, P0, b2, cheb_b, fc_w, fc_b, out);
}

// round 4
// speedup vs baseline: 3.3097x; 1.2524x over previous
#include <cuda_runtime.h>
#include <math.h>

#define N_NODES 50000
#define N_EDGES 1600000
#define D_IN    128
#define D_HID   50
#define D_OUT   10
#define STRIDE  64   // padded row stride (floats) for 50-dim node buffers

// ---------------- static scratch ----------------
__device__ float g_P [(size_t)5 * N_NODES * STRIDE];  // projections x @ W_k
__device__ float g_b3[(size_t)N_NODES * STRIDE];
__device__ float g_b2[(size_t)N_NODES * STRIDE];
__device__ float g_b1[(size_t)N_NODES * STRIDE];
__device__ int   g_deg   [N_NODES];
__device__ float g_dinv  [N_NODES];
__device__ int   g_rowptr[N_NODES + 1];
__device__ int   g_cursor[N_NODES];
__device__ int   g_bsum  [64];
__device__ int2  g_csr   [N_EDGES];                   // {col, w as float bits}
__device__ int   g_is64;

// ---------------- init: zero deg + dtype detect (block 0) ----------------
__global__ void init_kernel(const int* __restrict__ ei32) {
    int i = blockIdx.x * blockDim.x + threadIdx.x;
    if (i < N_NODES) g_deg[i] = 0;
    if (blockIdx.x == 0) {
        __shared__ int nz;
        if (threadIdx.x == 0) nz = 0;
        __syncthreads();
        // int64 edge_index with values<50000 has all-zero high words
        if (ei32[2 * threadIdx.x + 1] != 0) atomicExch(&nz, 1);
        __syncthreads();
        if (threadIdx.x == 0) g_is64 = (nz == 0) ? 1 : 0;
    }
}

// ---------------- degree: 2 edges per thread ----------------
__global__ void deg_kernel(const void* __restrict__ ei) {
    int t = blockIdx.x * blockDim.x + threadIdx.x;
    if (t >= N_EDGES / 2) return;
    int r0, r1;
    if (g_is64) {
        longlong2 v = __ldg((const longlong2*)ei + t);
        r0 = (int)v.x; r1 = (int)v.y;
    } else {
        int2 v = __ldg((const int2*)ei + t);
        r0 = v.x; r1 = v.y;
    }
    atomicAdd(&g_deg[r0], 1);
    atomicAdd(&g_deg[r1], 1);
}

// ---------------- scan phase 1: block-local exclusive scan + dinv ----------------
__global__ void __launch_bounds__(1024) scan1_kernel() {
    __shared__ int sm[1024];
    int tid = threadIdx.x;
    int idx = blockIdx.x * 1024 + tid;
    int d = (idx < N_NODES) ? g_deg[idx] : 0;
    if (idx < N_NODES) g_dinv[idx] = (d > 0) ? rsqrtf((float)d) : 0.0f;
    sm[tid] = d;
    __syncthreads();
    #pragma unroll
    for (int off = 1; off < 1024; off <<= 1) {
        int v = (tid >= off) ? sm[tid - off] : 0;
        __syncthreads();
        sm[tid] += v;
        __syncthreads();
    }
    if (idx < N_NODES) g_rowptr[idx] = sm[tid] - d;   // block-local exclusive
    if (tid == 1023) g_bsum[blockIdx.x] = sm[1023];
}

// ---------------- scan phase 2: add block offsets ----------------
__global__ void __launch_bounds__(1024) scan2_kernel() {
    __shared__ int sb[64];
    __shared__ int soff;
    int tid = threadIdx.x, bid = blockIdx.x;
    if (tid < 49) sb[tid] = g_bsum[tid];
    __syncthreads();
    if (tid == 0) {
        int o = 0;
        #pragma unroll 1
        for (int j = 0; j < bid; j++) o += sb[j];
        soff = o;
        if (bid == 0) g_rowptr[N_NODES] = N_EDGES;    // sum of degrees == E
    }
    __syncthreads();
    int idx = bid * 1024 + tid;
    if (idx < N_NODES) {
        int r = g_rowptr[idx] + soff;
        g_rowptr[idx] = r;
        g_cursor[idx] = r;
    }
}

// ---------------- scatter: 2 edges per thread ----------------
__global__ void scatter_kernel(const void* __restrict__ ei) {
    int t = blockIdx.x * blockDim.x + threadIdx.x;
    if (t >= N_EDGES / 2) return;
    int r0, r1, c0, c1;
    if (g_is64) {
        longlong2 rv = __ldg((const longlong2*)ei + t);
        longlong2 cv = __ldg((const longlong2*)ei + (N_EDGES / 2) + t);
        r0 = (int)rv.x; r1 = (int)rv.y; c0 = (int)cv.x; c1 = (int)cv.y;
    } else {
        int2 rv = __ldg((const int2*)ei + t);
        int2 cv = __ldg((const int2*)ei + (N_EDGES / 2) + t);
        r0 = rv.x; r1 = rv.y; c0 = cv.x; c1 = cv.y;
    }
    float w0 = -g_dinv[r0] * g_dinv[c0];
    float w1 = -g_dinv[r1] * g_dinv[c1];
    int p0 = atomicAdd(&g_cursor[r0], 1);
    g_csr[p0] = make_int2(c0, __float_as_int(w0));
    int p1 = atomicAdd(&g_cursor[r1], 1);
    g_csr[p1] = make_int2(c1, __float_as_int(w1));
}

// ---------------- f32x2 helpers ----------------
__device__ __forceinline__ unsigned long long pack2(float lo, float hi) {
    unsigned long long r;
    asm("mov.b64 %0, {%1, %2};" : "=l"(r) : "f"(lo), "f"(hi));
    return r;
}
__device__ __forceinline__ void unpack2(unsigned long long v, float& lo, float& hi) {
    asm("mov.b64 {%0, %1}, %2;" : "=f"(lo), "=f"(hi) : "l"(v));
}
#define FMA2(acc, a, b) asm("fma.rn.f32x2 %0, %1, %2, %0;" : "+l"(acc) : "l"(a), "l"(b))

// ---------------- projection: P_k[n,0:50] = x[n,0:128] @ W_k[128,50] ----------------
// 128 threads/block, 2 nodes per thread, packed-f32x2 FMAs.
__global__ void __launch_bounds__(128) proj_kernel(const float* __restrict__ x,
                                                   const float* __restrict__ cheb_w) {
    __shared__ __align__(16) float Wsm[D_IN * 52];
    int tid = threadIdx.x;
    int k = blockIdx.y;
    const float* W = cheb_w + (size_t)k * D_IN * D_HID;
    #pragma unroll 1
    for (int o = 0; o < D_HID; o++) Wsm[tid * 52 + o] = W[tid * D_HID + o];
    Wsm[tid * 52 + 50] = 0.0f;
    Wsm[tid * 52 + 51] = 0.0f;
    __syncthreads();

    int n0 = blockIdx.x * 256 + tid;
    int n1 = n0 + 128;
    bool v0 = n0 < N_NODES;
    bool v1 = n1 < N_NODES;

    unsigned long long acc0[26], acc1[26];
    #pragma unroll
    for (int p = 0; p < 26; p++) { acc0[p] = 0ull; acc1[p] = 0ull; }

    const float4* A0 = (const float4*)(x + (size_t)n0 * D_IN);
    const float4* A1 = (const float4*)(x + (size_t)n1 * D_IN);
    float4 z4 = make_float4(0.f, 0.f, 0.f, 0.f);
    float4 a0 = v0 ? __ldg(A0) : z4;
    float4 a1 = v1 ? __ldg(A1) : z4;

    #pragma unroll 1
    for (int ic = 0; ic < 32; ic++) {
        float4 a0n = z4, a1n = z4;
        if (ic < 31) {
            if (v0) a0n = __ldg(A0 + ic + 1);
            if (v1) a1n = __ldg(A1 + ic + 1);
        }
        float av0[4] = {a0.x, a0.y, a0.z, a0.w};
        float av1[4] = {a1.x, a1.y, a1.z, a1.w};
        #pragma unroll
        for (int j = 0; j < 4; j++) {
            unsigned long long a0p = pack2(av0[j], av0[j]);
            unsigned long long a1p = pack2(av1[j], av1[j]);
            const float4* wrow = (const float4*)(Wsm + (ic * 4 + j) * 52);
            #pragma unroll
            for (int q = 0; q < 13; q++) {
                float4 wv = wrow[q];
                unsigned long long w01 = pack2(wv.x, wv.y);
                unsigned long long w23 = pack2(wv.z, wv.w);
                FMA2(acc0[2 * q],     w01, a0p);
                FMA2(acc0[2 * q + 1], w23, a0p);
                FMA2(acc1[2 * q],     w01, a1p);
                FMA2(acc1[2 * q + 1], w23, a1p);
            }
        }
        a0 = a0n; a1 = a1n;
    }

    if (v0) {
        float* dst = g_P + ((size_t)k * N_NODES + n0) * STRIDE;
        #pragma unroll
        for (int q = 0; q < 12; q++) {
            float x0, x1, x2, x3;
            unpack2(acc0[2 * q], x0, x1);
            unpack2(acc0[2 * q + 1], x2, x3);
            ((float4*)dst)[q] = make_float4(x0, x1, x2, x3);
        }
        float x0, x1; unpack2(acc0[24], x0, x1);
        ((float2*)dst)[24] = make_float2(x0, x1);
    }
    if (v1) {
        float* dst = g_P + ((size_t)k * N_NODES + n1) * STRIDE;
        #pragma unroll
        for (int q = 0; q < 12; q++) {
            float x0, x1, x2, x3;
            unpack2(acc1[2 * q], x0, x1);
            unpack2(acc1[2 * q + 1], x2, x3);
            ((float4*)dst)[q] = make_float4(x0, x1, x2, x3);
        }
        float x0, x1; unpack2(acc1[24], x0, x1);
        ((float2*)dst)[24] = make_float2(x0, x1);
    }
}

// ---------------- shared accumulate: 8-edge unroll ----------------
__device__ __forceinline__ void row_accumulate(const float2* __restrict__ s2p,
                                               int s, int e, bool act, int lane,
                                               float& axo, float& ayo) {
    float ax0 = 0.f, ay0 = 0.f, ax1 = 0.f, ay1 = 0.f;
    int i = s;
    #pragma unroll 1
    for (; i + 8 <= e; i += 8) {
        int2 m[8];
        #pragma unroll
        for (int u = 0; u < 8; u++) m[u] = __ldg(&g_csr[i + u]);
        if (act) {
            float2 v[8];
            #pragma unroll
            for (int u = 0; u < 8; u++)
                v[u] = __ldg(s2p + (size_t)m[u].x * (STRIDE / 2) + lane);
            #pragma unroll
            for (int u = 0; u < 8; u++) {
                float w = __int_as_float(m[u].y);
                if (u & 1) { ax1 = fmaf(w, v[u].x, ax1); ay1 = fmaf(w, v[u].y, ay1); }
                else       { ax0 = fmaf(w, v[u].x, ax0); ay0 = fmaf(w, v[u].y, ay0); }
            }
        }
    }
    #pragma unroll 1
    for (; i + 2 <= e; i += 2) {
        int2 m0 = __ldg(&g_csr[i]);
        int2 m1 = __ldg(&g_csr[i + 1]);
        if (act) {
            float2 v0 = __ldg(s2p + (size_t)m0.x * (STRIDE / 2) + lane);
            float2 v1 = __ldg(s2p + (size_t)m1.x * (STRIDE / 2) + lane);
            float w0 = __int_as_float(m0.y), w1 = __int_as_float(m1.y);
            ax0 = fmaf(w0, v0.x, ax0); ay0 = fmaf(w0, v0.y, ay0);
            ax1 = fmaf(w1, v1.x, ax1); ay1 = fmaf(w1, v1.y, ay1);
        }
    }
    if (i < e) {
        int2 m = __ldg(&g_csr[i]);
        if (act) {
            float2 v = __ldg(s2p + (size_t)m.x * (STRIDE / 2) + lane);
            float w = __int_as_float(m.y);
            ax0 = fmaf(w, v.x, ax0); ay0 = fmaf(w, v.y, ay0);
        }
    }
    axo = ax0 + ax1;
    ayo = ay0 + ay1;
}

// ---------------- Clenshaw propagation (CSR, warp-per-row) ----------------
__global__ void __launch_bounds__(256) prop_csr(const float* __restrict__ src,
                                                const float* __restrict__ P,
                                                const float* __restrict__ sub, float scale,
                                                float* __restrict__ dst) {
    int gw = (blockIdx.x * blockDim.x + threadIdx.x) >> 5;
    int lane = threadIdx.x & 31;
    if (gw >= N_NODES) return;
    int s = __ldg(&g_rowptr[gw]);
    int e = __ldg(&g_rowptr[gw + 1]);
    const bool act = lane < 25;
    float ax, ay;
    row_accumulate((const float2*)src, s, e, act, lane, ax, ay);

    if (act) {
        size_t off = (size_t)gw * (STRIDE / 2) + lane;
        float2 p = __ldg((const float2*)P + off);
        float rx = fmaf(scale, ax, p.x);
        float ry = fmaf(scale, ay, p.y);
        if (sub) {
            float2 sb = __ldg((const float2*)sub + off);
            rx -= sb.x; ry -= sb.y;
        }
        ((float2*)dst)[off] = make_float2(rx, ry);
    }
}

// ---------------- last prop fused with head ----------------
__global__ void __launch_bounds__(256) prop_csr_head(const float* __restrict__ src,
                                                     const float* __restrict__ P,
                                                     const float* __restrict__ sub,
                                                     const float* __restrict__ cheb_b,
                                                     const float* __restrict__ fc_w,
                                                     const float* __restrict__ fc_b,
                                                     float* __restrict__ out) {
    __shared__ __align__(8) float s_fcwT[D_OUT * 52];
    __shared__ float s_b[D_HID];
    __shared__ float s_fcb[D_OUT];
    int tid = threadIdx.x;
    for (int i = tid; i < D_HID * D_OUT; i += blockDim.x) {
        int j = i / D_OUT, o = i % D_OUT;
        s_fcwT[o * 52 + j] = fc_w[i];
    }
    if (tid < D_OUT) { s_fcwT[tid * 52 + 50] = 0.f; s_fcwT[tid * 52 + 51] = 0.f; }
    if (tid < D_HID) s_b[tid] = cheb_b[tid];
    if (tid < D_OUT) s_fcb[tid] = fc_b[tid];
    __syncthreads();

    int gw = (blockIdx.x * blockDim.x + tid) >> 5;
    int lane = tid & 31;
    if (gw >= N_NODES) return;
    int s = __ldg(&g_rowptr[gw]);
    int e = __ldg(&g_rowptr[gw + 1]);
    const bool act = lane < 25;
    float ax, ay;
    row_accumulate((const float2*)src, s, e, act, lane, ax, ay);

    float l[D_OUT];
    if (act) {
        size_t off = (size_t)gw * (STRIDE / 2) + lane;
        float2 p  = __ldg((const float2*)P + off);
        float2 sb = __ldg((const float2*)sub + off);
        float hx = fmaxf(p.x + ax - sb.x + s_b[2 * lane],     0.0f);
        float hy = fmaxf(p.y + ay - sb.y + s_b[2 * lane + 1], 0.0f);
        #pragma unroll
        for (int o = 0; o < D_OUT; o++) {
            float2 w2 = ((const float2*)(s_fcwT + o * 52))[lane];
            l[o] = hx * w2.x + hy * w2.y;
        }
    } else {
        #pragma unroll
        for (int o = 0; o < D_OUT; o++) l[o] = 0.0f;
    }

    #pragma unroll
    for (int offm = 16; offm > 0; offm >>= 1) {
        #pragma unroll
        for (int o = 0; o < D_OUT; o++)
            l[o] += __shfl_xor_sync(0xffffffffu, l[o], offm);
    }

    if (lane == 0) {
        #pragma unroll
        for (int o = 0; o < D_OUT; o++) l[o] += s_fcb[o];
        float m = l[0];
        #pragma unroll
        for (int o = 1; o < D_OUT; o++) m = fmaxf(m, l[o]);
        float ssum = 0.0f;
        #pragma unroll
        for (int o = 0; o < D_OUT; o++) ssum += expf(l[o] - m);
        float lse = m + logf(ssum);
        float* orow = out + (size_t)gw * D_OUT;
        #pragma unroll
        for (int o = 0; o < D_OUT; o++) orow[o] = l[o] - lse;
    }
}

// ---------------- launch ----------------
extern "C" void kernel_launch(void* const* d_in, const int* in_sizes, int n_in,
                              void* d_out, int out_size) {
    const float* x      = (const float*)d_in[0];
    const void*  ei     = d_in[1];
    const float* cheb_w = (const float*)d_in[2];
    const float* cheb_b = (const float*)d_in[3];
    const float* fc_w   = (const float*)d_in[4];
    const float* fc_b   = (const float*)d_in[5];
    float* out = (float*)d_out;

    float *P, *b3, *b2, *b1;
    cudaGetSymbolAddress((void**)&P,  g_P);
    cudaGetSymbolAddress((void**)&b3, g_b3);
    cudaGetSymbolAddress((void**)&b2, g_b2);
    cudaGetSymbolAddress((void**)&b1, g_b1);
    const size_t PS = (size_t)N_NODES * STRIDE;
    float* P0 = P + 0 * PS;
    float* P1 = P + 1 * PS;
    float* P2 = P + 2 * PS;
    float* P3 = P + 3 * PS;
    float* P4 = P + 4 * PS;

    const int TB = 256;
    const int NODE_BLK = (N_NODES + TB - 1) / TB;
    const int HALF_EDGE_BLK = (N_EDGES / 2 + TB - 1) / TB;
    const int SCAN_BLK = (N_NODES + 1023) / 1024;   // 49
    const long long PT = (long long)N_NODES * 32;
    const int PROP_BLK = (int)((PT + TB - 1) / TB);
    dim3 pg((N_NODES + 255) / 256, 5);

    // lazily-created side stream for proj overlap (created once, outside capture)
    static cudaStream_t s_proj = nullptr;
    static cudaEvent_t ev_fork = nullptr, ev_proj = nullptr;
    static int use_async = -1;
    if (use_async < 0) {
        bool ok = (cudaStreamCreateWithFlags(&s_proj, cudaStreamNonBlocking) == cudaSuccess);
        ok = ok && (cudaEventCreateWithFlags(&ev_fork, cudaEventDisableTiming) == cudaSuccess);
        ok = ok && (cudaEventCreateWithFlags(&ev_proj, cudaEventDisableTiming) == cudaSuccess);
        use_async = ok ? 1 : 0;
    }

    // ---- fork: projections run concurrently with CSR build ----
    if (use_async) {
        cudaEventRecord(ev_fork, 0);
        cudaStreamWaitEvent(s_proj, ev_fork, 0);
        proj_kernel<<<pg, 128, 0, s_proj>>>(x, cheb_w);
        cudaEventRecord(ev_proj, s_proj);
    }

    // ---- CSR build (main stream) ----
    init_kernel<<<NODE_BLK, TB>>>((const int*)ei);
    deg_kernel<<<HALF_EDGE_BLK, TB>>>(ei);
    scan1_kernel<<<SCAN_BLK, 1024>>>();
    scan2_kernel<<<SCAN_BLK, 1024>>>();
    scatter_kernel<<<HALF_EDGE_BLK, TB>>>(ei);

    if (use_async) {
        cudaStreamWaitEvent(0, ev_proj, 0);   // join
    } else {
        proj_kernel<<<pg, 128>>>(x, cheb_w);
    }

    // ---- Clenshaw: b3 = P3 + 2L P4
    //      b2 = P2 + 2L b3 - P4
    //      b1 = P1 + 2L b2 - b3
    //      out = head(P0 + L b1 - b2)
    prop_csr<<<PROP_BLK, TB>>>(P4, P3, nullptr, 2.0f, b3);
    prop_csr<<<PROP_BLK, TB>>>(b3, P2, P4,      2.0f, b2);
    prop_csr<<<PROP_BLK, TB>>>(b2, P1, b3,      2.0f, b1);
    prop_csr_head<<<PROP_BLK, TB>>>(b1, P0, b2, cheb_b, fc_w, fc_b, out);
}

// round 5
// speedup vs baseline: 3.5694x; 1.0785x over previous
#include <cuda_runtime.h>
#include <cuda_fp16.h>
#include <math.h>

#define N_NODES 50000
#define N_EDGES 1600000
#define D_IN    128
#define D_HID   50
#define D_OUT   10
#define STRIDE  64   // fp32 row stride (floats) for P0..P3
#define HSTRIDE 32   // fp16 row stride (half2 units) = 128 bytes

// ---------------- static scratch ----------------
__device__ float g_P [(size_t)4 * N_NODES * STRIDE];              // P0..P3 fp32
__device__ __align__(128) __half2 g_P4h[(size_t)N_NODES * HSTRIDE];
__device__ __align__(128) __half2 g_b3h[(size_t)N_NODES * HSTRIDE];
__device__ __align__(128) __half2 g_b2h[(size_t)N_NODES * HSTRIDE];
__device__ __align__(128) __half2 g_b1h[(size_t)N_NODES * HSTRIDE];
__device__ int   g_deg   [N_NODES];
__device__ float g_dinv  [N_NODES];
__device__ int   g_rowptr[N_NODES + 1];
__device__ int   g_cursor[N_NODES];
__device__ int   g_bsum  [64];
__device__ int   g_scan_flag;
__device__ int2  g_csr   [N_EDGES];                               // {col, w bits}
__device__ int   g_is64;

// ---------------- init: zero deg + scan flag + dtype detect ----------------
__global__ void init_kernel(const int* __restrict__ ei32) {
    int i = blockIdx.x * blockDim.x + threadIdx.x;
    if (i < N_NODES) g_deg[i] = 0;
    if (blockIdx.x == 0) {
        __shared__ int nz;
        if (threadIdx.x == 0) { nz = 0; g_scan_flag = 0; }
        __syncthreads();
        if (ei32[2 * threadIdx.x + 1] != 0) atomicExch(&nz, 1);
        __syncthreads();
        if (threadIdx.x == 0) g_is64 = (nz == 0) ? 1 : 0;
    }
}

// ---------------- degree: 2 edges per thread ----------------
__global__ void deg_kernel(const void* __restrict__ ei) {
    int t = blockIdx.x * blockDim.x + threadIdx.x;
    if (t >= N_EDGES / 2) return;
    int r0, r1;
    if (g_is64) {
        longlong2 v = __ldg((const longlong2*)ei + t);
        r0 = (int)v.x; r1 = (int)v.y;
    } else {
        int2 v = __ldg((const int2*)ei + t);
        r0 = v.x; r1 = v.y;
    }
    atomicAdd(&g_deg[r0], 1);
    atomicAdd(&g_deg[r1], 1);
}

// ---------------- merged scan: block-local scan + grid spin-sync + offsets ----------------
__global__ void __launch_bounds__(1024) scan_kernel() {
    __shared__ int sm[1024];
    int tid = threadIdx.x, bid = blockIdx.x;
    int idx = bid * 1024 + tid;
    int d = (idx < N_NODES) ? g_deg[idx] : 0;
    if (idx < N_NODES) g_dinv[idx] = (d > 0) ? rsqrtf((float)d) : 0.0f;
    sm[tid] = d;
    __syncthreads();
    #pragma unroll
    for (int off = 1; off < 1024; off <<= 1) {
        int v = (tid >= off) ? sm[tid - off] : 0;
        __syncthreads();
        sm[tid] += v;
        __syncthreads();
    }
    int local_ex = sm[tid] - d;
    if (tid == 1023) {
        g_bsum[bid] = sm[1023];
        __threadfence();
        atomicAdd(&g_scan_flag, 1);
        // spin until all blocks have published their block sums
        while (*((volatile int*)&g_scan_flag) < gridDim.x) { }
    }
    __syncthreads();
    // block offset = sum of previous block sums (L2-coherent reads)
    __shared__ int soff;
    if (tid == 0) {
        int o = 0;
        #pragma unroll 1
        for (int j = 0; j < bid; j++) o += __ldcg(&g_bsum[j]);
        soff = o;
        if (bid == 0) g_rowptr[N_NODES] = N_EDGES;
    }
    __syncthreads();
    if (idx < N_NODES) {
        int r = local_ex + soff;
        g_rowptr[idx] = r;
        g_cursor[idx] = r;
    }
}

// ---------------- scatter: 2 edges per thread ----------------
__global__ void scatter_kernel(const void* __restrict__ ei) {
    int t = blockIdx.x * blockDim.x + threadIdx.x;
    if (t >= N_EDGES / 2) return;
    int r0, r1, c0, c1;
    if (g_is64) {
        longlong2 rv = __ldg((const longlong2*)ei + t);
        longlong2 cv = __ldg((const longlong2*)ei + (N_EDGES / 2) + t);
        r0 = (int)rv.x; r1 = (int)rv.y; c0 = (int)cv.x; c1 = (int)cv.y;
    } else {
        int2 rv = __ldg((const int2*)ei + t);
        int2 cv = __ldg((const int2*)ei + (N_EDGES / 2) + t);
        r0 = rv.x; r1 = rv.y; c0 = cv.x; c1 = cv.y;
    }
    float w0 = -g_dinv[r0] * g_dinv[c0];
    float w1 = -g_dinv[r1] * g_dinv[c1];
    int p0 = atomicAdd(&g_cursor[r0], 1);
    g_csr[p0] = make_int2(c0, __float_as_int(w0));
    int p1 = atomicAdd(&g_cursor[r1], 1);
    g_csr[p1] = make_int2(c1, __float_as_int(w1));
}

// ---------------- f32x2 helpers ----------------
__device__ __forceinline__ unsigned long long pack2(float lo, float hi) {
    unsigned long long r;
    asm("mov.b64 %0, {%1, %2};" : "=l"(r) : "f"(lo), "f"(hi));
    return r;
}
__device__ __forceinline__ void unpack2(unsigned long long v, float& lo, float& hi) {
    asm("mov.b64 {%0, %1}, %2;" : "=f"(lo), "=f"(hi) : "l"(v));
}
#define FMA2(acc, a, b) asm("fma.rn.f32x2 %0, %1, %2, %0;" : "+l"(acc) : "l"(a), "l"(b))

// ---------------- projection: P_k = x @ W_k; k<4 -> fp32, k==4 -> fp16 ----------------
__global__ void __launch_bounds__(128) proj_kernel(const float* __restrict__ x,
                                                   const float* __restrict__ cheb_w) {
    __shared__ __align__(16) float Wsm[D_IN * 52];
    int tid = threadIdx.x;
    int k = blockIdx.y;
    const float* W = cheb_w + (size_t)k * D_IN * D_HID;
    #pragma unroll 1
    for (int o = 0; o < D_HID; o++) Wsm[tid * 52 + o] = W[tid * D_HID + o];
    Wsm[tid * 52 + 50] = 0.0f;
    Wsm[tid * 52 + 51] = 0.0f;
    __syncthreads();

    int n0 = blockIdx.x * 256 + tid;
    int n1 = n0 + 128;
    bool v0 = n0 < N_NODES;
    bool v1 = n1 < N_NODES;

    unsigned long long acc0[26], acc1[26];
    #pragma unroll
    for (int p = 0; p < 26; p++) { acc0[p] = 0ull; acc1[p] = 0ull; }

    const float4* A0 = (const float4*)(x + (size_t)n0 * D_IN);
    const float4* A1 = (const float4*)(x + (size_t)n1 * D_IN);
    float4 z4 = make_float4(0.f, 0.f, 0.f, 0.f);
    float4 a0 = v0 ? __ldg(A0) : z4;
    float4 a1 = v1 ? __ldg(A1) : z4;

    #pragma unroll 1
    for (int ic = 0; ic < 32; ic++) {
        float4 a0n = z4, a1n = z4;
        if (ic < 31) {
            if (v0) a0n = __ldg(A0 + ic + 1);
            if (v1) a1n = __ldg(A1 + ic + 1);
        }
        float av0[4] = {a0.x, a0.y, a0.z, a0.w};
        float av1[4] = {a1.x, a1.y, a1.z, a1.w};
        #pragma unroll
        for (int j = 0; j < 4; j++) {
            unsigned long long a0p = pack2(av0[j], av0[j]);
            unsigned long long a1p = pack2(av1[j], av1[j]);
            const float4* wrow = (const float4*)(Wsm + (ic * 4 + j) * 52);
            #pragma unroll
            for (int q = 0; q < 13; q++) {
                float4 wv = wrow[q];
                unsigned long long w01 = pack2(wv.x, wv.y);
                unsigned long long w23 = pack2(wv.z, wv.w);
                FMA2(acc0[2 * q],     w01, a0p);
                FMA2(acc0[2 * q + 1], w23, a0p);
                FMA2(acc1[2 * q],     w01, a1p);
                FMA2(acc1[2 * q + 1], w23, a1p);
            }
        }
        a0 = a0n; a1 = a1n;
    }

    #pragma unroll
    for (int which = 0; which < 2; which++) {
        bool v = which ? v1 : v0;
        int n = which ? n1 : n0;
        unsigned long long* acc = which ? acc1 : acc0;
        if (!v) continue;
        if (k < 4) {
            float* dst = g_P + ((size_t)k * N_NODES + n) * STRIDE;
            #pragma unroll
            for (int q = 0; q < 12; q++) {
                float x0, x1, x2, x3;
                unpack2(acc[2 * q], x0, x1);
                unpack2(acc[2 * q + 1], x2, x3);
                ((float4*)dst)[q] = make_float4(x0, x1, x2, x3);
            }
            float x0, x1; unpack2(acc[24], x0, x1);
            ((float2*)dst)[24] = make_float2(x0, x1);
        } else {
            __half2* dst = g_P4h + (size_t)n * HSTRIDE;
            #pragma unroll
            for (int p = 0; p < 12; p++) {   // pairs of half2 -> 8B stores
                float x0, x1, x2, x3;
                unpack2(acc[2 * p], x0, x1);
                unpack2(acc[2 * p + 1], x2, x3);
                __half2 h0 = __floats2half2_rn(x0, x1);
                __half2 h1 = __floats2half2_rn(x2, x3);
                uint2 u; u.x = *(unsigned*)&h0; u.y = *(unsigned*)&h1;
                ((uint2*)dst)[p] = u;
            }
            float x0, x1; unpack2(acc[24], x0, x1);
            dst[24] = __floats2half2_rn(x0, x1);
        }
    }
}

// ---------------- fp16 gather accumulate: 8-edge unroll ----------------
__device__ __forceinline__ void row_accumulate_h(const __half2* __restrict__ srch,
                                                 int s, int e, bool act, int lane,
                                                 float& axo, float& ayo) {
    float ax0 = 0.f, ay0 = 0.f, ax1 = 0.f, ay1 = 0.f;
    int i = s;
    #pragma unroll 1
    for (; i + 8 <= e; i += 8) {
        int2 m[8];
        #pragma unroll
        for (int u = 0; u < 8; u++) m[u] = __ldg(&g_csr[i + u]);
        if (act) {
            __half2 v[8];
            #pragma unroll
            for (int u = 0; u < 8; u++)
                v[u] = __ldg(srch + (size_t)m[u].x * HSTRIDE + lane);
            #pragma unroll
            for (int u = 0; u < 8; u++) {
                float w = __int_as_float(m[u].y);
                float2 vf = __half22float2(v[u]);
                if (u & 1) { ax1 = fmaf(w, vf.x, ax1); ay1 = fmaf(w, vf.y, ay1); }
                else       { ax0 = fmaf(w, vf.x, ax0); ay0 = fmaf(w, vf.y, ay0); }
            }
        }
    }
    #pragma unroll 1
    for (; i + 2 <= e; i += 2) {
        int2 m0 = __ldg(&g_csr[i]);
        int2 m1 = __ldg(&g_csr[i + 1]);
        if (act) {
            float2 v0 = __half22float2(__ldg(srch + (size_t)m0.x * HSTRIDE + lane));
            float2 v1 = __half22float2(__ldg(srch + (size_t)m1.x * HSTRIDE + lane));
            float w0 = __int_as_float(m0.y), w1 = __int_as_float(m1.y);
            ax0 = fmaf(w0, v0.x, ax0); ay0 = fmaf(w0, v0.y, ay0);
            ax1 = fmaf(w1, v1.x, ax1); ay1 = fmaf(w1, v1.y, ay1);
        }
    }
    if (i < e) {
        int2 m = __ldg(&g_csr[i]);
        if (act) {
            float2 v = __half22float2(__ldg(srch + (size_t)m.x * HSTRIDE + lane));
            float w = __int_as_float(m.y);
            ax0 = fmaf(w, v.x, ax0); ay0 = fmaf(w, v.y, ay0);
        }
    }
    axo = ax0 + ax1;
    ayo = ay0 + ay1;
}

// ---------------- Clenshaw propagation (fp16 gather/store, fp32 math) ----------------
// dst[row] = P[row] + scale * sum_e w_e * src[col_e] - (sub ? sub[row] : 0)
__global__ void __launch_bounds__(256) prop_csr_h(const __half2* __restrict__ src,
                                                  const float* __restrict__ P,
                                                  const __half2* __restrict__ sub, float scale,
                                                  __half2* __restrict__ dst) {
    int gw = (blockIdx.x * blockDim.x + threadIdx.x) >> 5;
    int lane = threadIdx.x & 31;
    if (gw >= N_NODES) return;
    int s = __ldg(&g_rowptr[gw]);
    int e = __ldg(&g_rowptr[gw + 1]);
    const bool act = lane < 25;
    float ax, ay;
    row_accumulate_h(src, s, e, act, lane, ax, ay);

    if (act) {
        size_t hoff = (size_t)gw * HSTRIDE + lane;
        float2 p = __ldg((const float2*)P + (size_t)gw * (STRIDE / 2) + lane);
        float rx = fmaf(scale, ax, p.x);
        float ry = fmaf(scale, ay, p.y);
        if (sub) {
            float2 sb = __half22float2(__ldg(sub + hoff));
            rx -= sb.x; ry -= sb.y;
        }
        dst[hoff] = __floats2half2_rn(rx, ry);
    }
}

// ---------------- last prop fused with head ----------------
__global__ void __launch_bounds__(256) prop_csr_head(const __half2* __restrict__ src,
                                                     const float* __restrict__ P,
                                                     const __half2* __restrict__ sub,
                                                     const float* __restrict__ cheb_b,
                                                     const float* __restrict__ fc_w,
                                                     const float* __restrict__ fc_b,
                                                     float* __restrict__ out) {
    __shared__ __align__(8) float s_fcwT[D_OUT * 52];
    __shared__ float s_b[D_HID];
    __shared__ float s_fcb[D_OUT];
    int tid = threadIdx.x;
    for (int i = tid; i < D_HID * D_OUT; i += blockDim.x) {
        int j = i / D_OUT, o = i % D_OUT;
        s_fcwT[o * 52 + j] = fc_w[i];
    }
    if (tid < D_OUT) { s_fcwT[tid * 52 + 50] = 0.f; s_fcwT[tid * 52 + 51] = 0.f; }
    if (tid < D_HID) s_b[tid] = cheb_b[tid];
    if (tid < D_OUT) s_fcb[tid] = fc_b[tid];
    __syncthreads();

    int gw = (blockIdx.x * blockDim.x + tid) >> 5;
    int lane = tid & 31;
    if (gw >= N_NODES) return;
    int s = __ldg(&g_rowptr[gw]);
    int e = __ldg(&g_rowptr[gw + 1]);
    const bool act = lane < 25;
    float ax, ay;
    row_accumulate_h(src, s, e, act, lane, ax, ay);

    float l[D_OUT];
    if (act) {
        float2 p  = __ldg((const float2*)P + (size_t)gw * (STRIDE / 2) + lane);
        float2 sb = __half22float2(__ldg(sub + (size_t)gw * HSTRIDE + lane));
        float hx = fmaxf(p.x + ax - sb.x + s_b[2 * lane],     0.0f);   // scale = 1
        float hy = fmaxf(p.y + ay - sb.y + s_b[2 * lane + 1], 0.0f);
        #pragma unroll
        for (int o = 0; o < D_OUT; o++) {
            float2 w2 = ((const float2*)(s_fcwT + o * 52))[lane];
            l[o] = hx * w2.x + hy * w2.y;
        }
    } else {
        #pragma unroll
        for (int o = 0; o < D_OUT; o++) l[o] = 0.0f;
    }

    #pragma unroll
    for (int offm = 16; offm > 0; offm >>= 1) {
        #pragma unroll
        for (int o = 0; o < D_OUT; o++)
            l[o] += __shfl_xor_sync(0xffffffffu, l[o], offm);
    }

    if (lane == 0) {
        #pragma unroll
        for (int o = 0; o < D_OUT; o++) l[o] += s_fcb[o];
        float m = l[0];
        #pragma unroll
        for (int o = 1; o < D_OUT; o++) m = fmaxf(m, l[o]);
        float ssum = 0.0f;
        #pragma unroll
        for (int o = 0; o < D_OUT; o++) ssum += expf(l[o] - m);
        float lse = m + logf(ssum);
        float* orow = out + (size_t)gw * D_OUT;
        #pragma unroll
        for (int o = 0; o < D_OUT; o++) orow[o] = l[o] - lse;
    }
}

// ---------------- launch ----------------
extern "C" void kernel_launch(void* const* d_in, const int* in_sizes, int n_in,
                              void* d_out, int out_size) {
    const float* x      = (const float*)d_in[0];
    const void*  ei     = d_in[1];
    const float* cheb_w = (const float*)d_in[2];
    const float* cheb_b = (const float*)d_in[3];
    const float* fc_w   = (const float*)d_in[4];
    const float* fc_b   = (const float*)d_in[5];
    float* out = (float*)d_out;

    float *P;
    __half2 *P4h, *b3h, *b2h, *b1h;
    cudaGetSymbolAddress((void**)&P,   g_P);
    cudaGetSymbolAddress((void**)&P4h, g_P4h);
    cudaGetSymbolAddress((void**)&b3h, g_b3h);
    cudaGetSymbolAddress((void**)&b2h, g_b2h);
    cudaGetSymbolAddress((void**)&b1h, g_b1h);
    const size_t PS = (size_t)N_NODES * STRIDE;
    float* P0 = P + 0 * PS;
    float* P1 = P + 1 * PS;
    float* P2 = P + 2 * PS;
    float* P3 = P + 3 * PS;

    const int TB = 256;
    const int NODE_BLK = (N_NODES + TB - 1) / TB;
    const int HALF_EDGE_BLK = (N_EDGES / 2 + TB - 1) / TB;
    const int SCAN_BLK = (N_NODES + 1023) / 1024;   // 49
    const long long PT = (long long)N_NODES * 32;
    const int PROP_BLK = (int)((PT + TB - 1) / TB);
    dim3 pg((N_NODES + 255) / 256, 5);

    static cudaStream_t s_proj = nullptr;
    static cudaEvent_t ev_fork = nullptr, ev_proj = nullptr;
    static int use_async = -1;
    if (use_async < 0) {
        bool ok = (cudaStreamCreateWithFlags(&s_proj, cudaStreamNonBlocking) == cudaSuccess);
        ok = ok && (cudaEventCreateWithFlags(&ev_fork, cudaEventDisableTiming) == cudaSuccess);
        ok = ok && (cudaEventCreateWithFlags(&ev_proj, cudaEventDisableTiming) == cudaSuccess);
        use_async = ok ? 1 : 0;
    }

    // ---- fork: projections run concurrently with CSR build ----
    if (use_async) {
        cudaEventRecord(ev_fork, 0);
        cudaStreamWaitEvent(s_proj, ev_fork, 0);
        proj_kernel<<<pg, 128, 0, s_proj>>>(x, cheb_w);
        cudaEventRecord(ev_proj, s_proj);
    }

    // ---- CSR build (main stream) ----
    init_kernel<<<NODE_BLK, TB>>>((const int*)ei);
    deg_kernel<<<HALF_EDGE_BLK, TB>>>(ei);
    scan_kernel<<<SCAN_BLK, 1024>>>();
    scatter_kernel<<<HALF_EDGE_BLK, TB>>>(ei);

    if (use_async) {
        cudaStreamWaitEvent(0, ev_proj, 0);   // join
    } else {
        proj_kernel<<<pg, 128>>>(x, cheb_w);
    }

    // ---- Clenshaw: b3 = P3 + 2L P4
    //      b2 = P2 + 2L b3 - P4
    //      b1 = P1 + 2L b2 - b3
    //      out = head(P0 + L b1 - b2)
    prop_csr_h<<<PROP_BLK, TB>>>(P4h, P3, nullptr, 2.0f, b3h);
    prop_csr_h<<<PROP_BLK, TB>>>(b3h, P2, P4h,     2.0f, b2h);
    prop_csr_h<<<PROP_BLK, TB>>>(b2h, P1, b3h,     2.0f, b1h);
    prop_csr_head<<<PROP_BLK, TB>>>(b1h, P0, b2h, cheb_b, fc_w, fc_b, out);
}